// round 2
// baseline (speedup 1.0000x reference)
#include <cuda_runtime.h>

// out[i] = cos(x[i,0] + w0), x: [N,2] float32 interleaved, N = 16777216 (2^24).
// Pure streaming map: read 128MB, write 64MB. Target DRAM-saturated.
// Each thread: 8 samples = 4x float4 streaming loads (MLP=4), 2x float4 streaming stores.
// Exact grid, no grid-stride loop.

__global__ void __launch_bounds__(256)
hybrid_qnn_cos_kernel(const float4* __restrict__ x4,   // N/2 float4s (each = 2 samples)
                      const float* __restrict__ w,
                      float4* __restrict__ out4,       // N/4 float4s
                      int n_thread)                     // N/8 threads
{
    int t = blockIdx.x * blockDim.x + threadIdx.x;
    if (t >= n_thread) return;

    const float w0 = __ldg(w);

    // Front-batch all 4 loads for MLP=4 before any dependent math.
    const float4* p = x4 + (size_t)t * 4;
    float4 a = __ldcs(p + 0);
    float4 b = __ldcs(p + 1);
    float4 c = __ldcs(p + 2);
    float4 d = __ldcs(p + 3);

    float4 o0, o1;
    o0.x = cosf(a.x + w0);
    o0.y = cosf(a.z + w0);
    o0.z = cosf(b.x + w0);
    o0.w = cosf(b.z + w0);
    o1.x = cosf(c.x + w0);
    o1.y = cosf(c.z + w0);
    o1.z = cosf(d.x + w0);
    o1.w = cosf(d.z + w0);

    float4* q = out4 + (size_t)t * 2;
    __stcs(q + 0, o0);
    __stcs(q + 1, o1);
}

extern "C" void kernel_launch(void* const* d_in, const int* in_sizes, int n_in,
                              void* d_out, int out_size)
{
    const float4* x4 = (const float4*)d_in[0];   // x: [N,2] float32
    const float*  w  = (const float*)d_in[1];    // weights: [2] float32
    float4* out4 = (float4*)d_out;

    int n = in_sizes[0] / 2;        // N samples
    int n_thread = n / 8;           // 8 samples per thread (N = 2^24, divisible)

    const int threads = 256;
    int blocks = (n_thread + threads - 1) / threads;   // 8192 blocks

    hybrid_qnn_cos_kernel<<<blocks, threads>>>(x4, w, out4, n_thread);
}

// round 3
// speedup vs baseline: 1.1834x; 1.1834x over previous
#include <cuda_runtime.h>

// out[i] = cos(x[i,0] + w0), x: [N,2] float32 interleaved, N = 16777216 (2^24).
// Memory-bound streaming map: read 128MB (x), write 64MB (out).
// R1 structure (proven 29.9us): 2x __ldg float4 loads + 1 float4 store per thread,
// 16384 blocks x 256 threads, single grid-stride iteration.
// R3 change: streaming store hint (__stcs) only — output is write-once, keep it
// evict-first in L2 so the write stream doesn't thrash the read stream.

__global__ void __launch_bounds__(256, 8)
hybrid_qnn_cos_kernel(const float4* __restrict__ x4,   // N/2 float4s (each = 2 samples)
                      const float* __restrict__ w,
                      float4* __restrict__ out4,       // N/4 float4s
                      int n_out4)                       // N/4
{
    const float w0 = __ldg(w);
    int idx = blockIdx.x * blockDim.x + threadIdx.x;
    int stride = gridDim.x * blockDim.x;

    for (int i = idx; i < n_out4; i += stride) {
        // samples 4i .. 4i+3  ->  x4[2i] = {x[4i,0],x[4i,1],x[4i+1,0],x[4i+1,1]}
        float4 a = __ldg(&x4[2 * i]);
        float4 b = __ldg(&x4[2 * i + 1]);
        float4 o;
        o.x = cosf(a.x + w0);
        o.y = cosf(a.z + w0);
        o.z = cosf(b.x + w0);
        o.w = cosf(b.z + w0);
        __stcs(&out4[i], o);
    }
}

extern "C" void kernel_launch(void* const* d_in, const int* in_sizes, int n_in,
                              void* d_out, int out_size)
{
    const float4* x4 = (const float4*)d_in[0];   // x: [N,2] float32
    const float*  w  = (const float*)d_in[1];    // weights: [2] float32
    float4* out4 = (float4*)d_out;

    int n = in_sizes[0] / 2;        // number of samples N
    int n_out4 = n / 4;             // N divisible by 4 (N = 2^24)

    const int threads = 256;
    int blocks = (n_out4 + threads - 1) / threads;
    if (blocks > 16384) blocks = 16384;

    hybrid_qnn_cos_kernel<<<blocks, threads>>>(x4, w, out4, n_out4);
}